// round 16
// baseline (speedup 1.0000x reference)
#include <cuda_runtime.h>
#include <cuda_fp16.h>
#include <math.h>
#include <stdint.h>

// Problem constants
#define BQ    8192
#define DQ    1024
#define HQ    4096
#define H2Q   2048
#define DOUTQ 1024
#define EQ    8
#define GQ    512
#define PAIRS (BQ * 2)
#define MAXTILES (PAIRS / 128 + EQ)   // 136

// ---------------- scratch (device globals) ---------------------------------
__device__ float g_g[BQ * GQ];
__device__ float g_y [PAIRS * DOUTQ];
__device__ float g_gatew[BQ * EQ];
__device__ int   g_topidx[BQ * 2];
__device__ float g_topw [BQ * 2];
__device__ int   g_cnt[EQ];
__device__ int   g_off[EQ + 1];
__device__ int   g_cursor[EQ];
__device__ int   g_ptok[PAIRS];
__device__ int   g_pidx[BQ * 2];
__device__ int   g_tiles[MAXTILES];
__device__ int   g_ntiles;

// fp16 operands
__device__ __half g_x  [BQ * DQ];          // x hi
__device__ __half g_xl [BQ * DQ];          // x lo (gate only)
__device__ __half g_wg1h[GQ * DQ];         // Wg1^T hi
__device__ __half g_wg1l[GQ * DQ];         // Wg1^T lo
__device__ __half g_w1h[EQ * DQ * HQ];
__device__ __half g_w2h[EQ * HQ * H2Q];
__device__ __half g_w3h[EQ * H2Q * DOUTQ];
__device__ __half g_h1 [PAIRS * HQ];
__device__ __half g_h2 [PAIRS * H2Q];

// ---------------- helpers ---------------------------------------------------
__device__ __forceinline__ uint32_t smem_u32(const void* p) {
    uint32_t a;
    asm("{ .reg .u64 t; cvta.to.shared.u64 t, %1; cvt.u32.u64 %0, t; }"
        : "=r"(a) : "l"(p));
    return a;
}
__device__ __forceinline__ uint32_t sw64(uint32_t off) {
    return off ^ ((off >> 3) & 0x30);
}
__device__ __forceinline__ uint32_t sw128(uint32_t off) {
    return off ^ ((off >> 3) & 0x70);
}
__device__ __forceinline__ void ldsm_x4(uint32_t* r, uint32_t addr) {
    asm volatile("ldmatrix.sync.aligned.m8n8.x4.shared.b16 {%0,%1,%2,%3}, [%4];"
                 : "=r"(r[0]), "=r"(r[1]), "=r"(r[2]), "=r"(r[3]) : "r"(addr));
}
__device__ __forceinline__ void mma_f16(float* d, const uint32_t* a,
                                        uint32_t b0, uint32_t b1) {
    asm volatile(
        "mma.sync.aligned.m16n8k16.row.col.f32.f16.f16.f32 "
        "{%0,%1,%2,%3}, {%4,%5,%6,%7}, {%8,%9}, {%0,%1,%2,%3};"
        : "+f"(d[0]), "+f"(d[1]), "+f"(d[2]), "+f"(d[3])
        : "r"(a[0]), "r"(a[1]), "r"(a[2]), "r"(a[3]), "r"(b0), "r"(b1));
}
__device__ __forceinline__ void cpa16(uint32_t d, const void* s) {
    asm volatile("cp.async.cg.shared.global [%0], [%1], 16;" :: "r"(d), "l"(s));
}
#define CP_COMMIT() asm volatile("cp.async.commit_group;" ::: "memory")
#define CP_WAIT1()  asm volatile("cp.async.wait_group 1;" ::: "memory")
#define CP_WAIT0()  asm volatile("cp.async.wait_group 0;" ::: "memory")

#define TM 128
#define TN 128

// ---------------- expert fp16 GEMM (single term, TK=64, 8Mx1N warps) --------
#define TKE    64
#define O_A    0                 // 128 rows x 128B = 16384
#define O_B    16384
#define STG_SZ 32768
#define SMEM_SZ (3 * STG_SZ)     // 98304

__global__ __launch_bounds__(256, 2) void moe_f16_gemm(
    const __half* __restrict__ Ax,
    const __half* __restrict__ Bh,
    const float* __restrict__ bias,
    __half* __restrict__ Chf,
    float* __restrict__ Cf,
    const int* __restrict__ rowmap,
    int K, int N, int relu)
{
    extern __shared__ char smem[];
    if ((int)blockIdx.y >= g_ntiles) return;
    const int d    = g_tiles[blockIdx.y];
    const int e    = d & 255;
    const int ts   = d >> 8;
    const int mseg = g_off[e];
    const int mend = mseg + g_cnt[e];
    const int m0   = mseg + ts * TM;
    const int n0   = blockIdx.x * TN;

    const __half* Bhe = Bh + (long)e * (long)N * (long)K;
    const float* bvec = bias + (long)e * N;

    const uint32_t sb = smem_u32(smem);
    const int tid  = threadIdx.x;
    const int wid  = tid >> 5;     // 8 warps, each 16M x 128N
    const int lane = tid & 31;

    float acc[16][4];              // [nt*2 + half][4]
#pragma unroll
    for (int i = 0; i < 16; i++)
#pragma unroll
        for (int j = 0; j < 4; j++) acc[i][j] = 0.f;

    const int lr = ((lane >> 3) & 1) * 8 + (lane & 7);
    const int lc = (lane >> 4) * 16;

    // base swizzled offsets (k-step applied via XOR of ks*32)
    const uint32_t offA = sw128((uint32_t)((wid * 16 + lr) * 128 + lc));
    uint32_t offB[8];
#pragma unroll
    for (int nt = 0; nt < 8; nt++)
        offB[nt] = sw128((uint32_t)((nt * 16 + lr) * 128 + lc));

    const int nk = K / TKE;

#define LOAD_CHUNK(kc_)                                                       \
    do {                                                                      \
        const uint32_t base_ = sb + ((kc_) % 3) * STG_SZ;                     \
        const int kbase_ = (kc_) * TKE;                                       \
        _Pragma("unroll")                                                     \
        for (int i = 0; i < 4; i++) {        /* A: 1024 16B chunks */         \
            int u = tid + i * 256;                                            \
            int r = u >> 3;                                                   \
            int c = u & 7;                                                    \
            int gm = m0 + r;                                                  \
            if (gm >= mend) gm = mend - 1;                                    \
            int src = rowmap ? rowmap[gm] : gm;                               \
            const __half* g = Ax + (long)src * K + kbase_ + c * 8;            \
            uint32_t dd = base_ + O_A + sw128((uint32_t)(r * 128 + c * 16));  \
            cpa16(dd, g);                                                     \
        }                                                                     \
        _Pragma("unroll")                                                     \
        for (int i = 0; i < 4; i++) {        /* B: 1024 16B chunks */         \
            int u = tid + i * 256;                                            \
            int r = u >> 3;                                                   \
            int c = u & 7;                                                    \
            const __half* g = Bhe + (long)(n0 + r) * K + kbase_ + c * 8;      \
            uint32_t dd = base_ + O_B + sw128((uint32_t)(r * 128 + c * 16));  \
            cpa16(dd, g);                                                     \
        }                                                                     \
        CP_COMMIT();                                                          \
    } while (0)

    LOAD_CHUNK(0);
    if (nk > 1) LOAD_CHUNK(1);

    for (int kc = 0; kc < nk; kc++) {
        if (kc == nk - 1) { CP_WAIT0(); } else { CP_WAIT1(); }
        __syncthreads();
        if (kc + 2 < nk) LOAD_CHUNK(kc + 2);

        const uint32_t base = sb + (kc % 3) * STG_SZ;
#pragma unroll
        for (int ks = 0; ks < 4; ks++) {
            const uint32_t kx = (uint32_t)(ks << 5);
            uint32_t af[4];
            ldsm_x4(af, base + O_A + (offA ^ kx));
            // B frags in two groups of 4 (register pressure)
#pragma unroll
            for (int gp = 0; gp < 2; gp++) {
                uint32_t bfrag[4][4];
#pragma unroll
                for (int j = 0; j < 4; j++)
                    ldsm_x4(bfrag[j], base + O_B + (offB[gp * 4 + j] ^ kx));
#pragma unroll
                for (int j = 0; j < 4; j++) {
                    const int nt = gp * 4 + j;
                    mma_f16(acc[nt * 2 + 0], af, bfrag[j][0], bfrag[j][2]);
                    mma_f16(acc[nt * 2 + 1], af, bfrag[j][1], bfrag[j][3]);
                }
            }
        }
    }
#undef LOAD_CHUNK

    // ---- epilogue: warp covers rows m0+wid*16..+15, cols n0..n0+127
    {
        const int row0 = m0 + wid * 16 + (lane >> 2);
        const int row1 = row0 + 8;
#pragma unroll
        for (int i = 0; i < 16; i++) {
            const float* a4 = acc[i];
            const int nt = i >> 1, half = i & 1;
            int col = n0 + nt * 16 + half * 8 + ((lane & 3) << 1);
            float bb0 = bvec[col], bb1 = bvec[col + 1];
            float v0 = a4[0] + bb0, v1 = a4[1] + bb1;
            float v2 = a4[2] + bb0, v3 = a4[3] + bb1;
            if (relu) {
                v0 = fmaxf(v0, 0.f); v1 = fmaxf(v1, 0.f);
                v2 = fmaxf(v2, 0.f); v3 = fmaxf(v3, 0.f);
            }
            if (Cf) {
                if (row0 < mend)
                    *reinterpret_cast<float2*>(Cf + (long)row0 * N + col) = make_float2(v0, v1);
                if (row1 < mend)
                    *reinterpret_cast<float2*>(Cf + (long)row1 * N + col) = make_float2(v2, v3);
            } else {
                if (row0 < mend) {
                    __half2 h;
                    h.x = __float2half_rn(v0); h.y = __float2half_rn(v1);
                    *reinterpret_cast<uint32_t*>(Chf + (long)row0 * N + col) =
                        *reinterpret_cast<uint32_t*>(&h);
                }
                if (row1 < mend) {
                    __half2 h;
                    h.x = __float2half_rn(v2); h.y = __float2half_rn(v3);
                    *reinterpret_cast<uint32_t*>(Chf + (long)row1 * N + col) =
                        *reinterpret_cast<uint32_t*>(&h);
                }
            }
        }
    }
}

// ---------------- gate layer-1 GEMM (3-term fp16, ~fp32 precision) ----------
#define GO_AH  0
#define GO_AL  8192
#define GO_BH  16384
#define GO_BL  24576
#define GSTG   32768
#define GSMEM  (3 * GSTG)        // 98304
#define GTK    32

__global__ __launch_bounds__(256, 2) void gate_f16_gemm(
    const float* __restrict__ bias)
{
    extern __shared__ char smem[];
    const int m0 = blockIdx.y * TM;
    const int n0 = blockIdx.x * TN;
    const int K  = DQ, N = GQ;

    const uint32_t sb = smem_u32(smem);
    const int tid  = threadIdx.x;
    const int wid  = tid >> 5;
    const int lane = tid & 31;
    const int wm   = wid & 3;
    const int wn   = wid >> 2;

    float acc[16][4];
#pragma unroll
    for (int i = 0; i < 16; i++)
#pragma unroll
        for (int j = 0; j < 4; j++) acc[i][j] = 0.f;

    const int lr = ((lane >> 3) & 1) * 8 + (lane & 7);
    const int lc = (lane >> 4) * 16;

    uint32_t offA[2][2], offB[2][4];
#pragma unroll
    for (int ks = 0; ks < 2; ks++) {
        const int kb = ks * 32 + lc;
#pragma unroll
        for (int mt = 0; mt < 2; mt++)
            offA[ks][mt] = sw64((uint32_t)((wm * 32 + mt * 16 + lr) * 64 + kb));
#pragma unroll
        for (int nt = 0; nt < 4; nt++)
            offB[ks][nt] = sw64((uint32_t)((wn * 64 + nt * 16 + lr) * 64 + kb));
    }

    const int nk = K / GTK;   // 32

#define GLOAD(kc_)                                                            \
    do {                                                                      \
        const uint32_t base_ = sb + ((kc_) % 3) * GSTG;                       \
        const int kbase_ = (kc_) * GTK;                                       \
        _Pragma("unroll")                                                     \
        for (int i = 0; i < 4; i++) {     /* A hi+lo */                       \
            int u     = tid + i * 256;                                        \
            int half_ = u >> 9;                                               \
            int v     = u & 511;                                              \
            int r     = v >> 2;                                               \
            int c     = v & 3;                                                \
            const __half* g = (half_ ? g_xl : g_x) + (long)(m0 + r) * K + kbase_ + c * 8; \
            uint32_t dd = base_ + (half_ ? GO_AL : GO_AH) + sw64((uint32_t)(r * 64 + c * 16)); \
            cpa16(dd, g);                                                     \
        }                                                                     \
        _Pragma("unroll")                                                     \
        for (int i = 0; i < 4; i++) {     /* B hi+lo */                       \
            int u     = tid + i * 256;                                        \
            int half_ = u >> 9;                                               \
            int v     = u & 511;                                              \
            int r     = v >> 2;                                               \
            int c     = v & 3;                                                \
            const __half* g = (half_ ? g_wg1l : g_wg1h) + (long)(n0 + r) * K + kbase_ + c * 8; \
            uint32_t dd = base_ + (half_ ? GO_BL : GO_BH) + sw64((uint32_t)(r * 64 + c * 16)); \
            cpa16(dd, g);                                                     \
        }                                                                     \
        CP_COMMIT();                                                          \
    } while (0)

    GLOAD(0);
    GLOAD(1);

    for (int kc = 0; kc < nk; kc++) {
        if (kc == nk - 1) { CP_WAIT0(); } else { CP_WAIT1(); }
        __syncthreads();
        if (kc + 2 < nk) GLOAD(kc + 2);

        const uint32_t base = sb + (kc % 3) * GSTG;
#pragma unroll
        for (int ks = 0; ks < 2; ks++) {
            uint32_t ah[2][4], al[2][4], bfrag[4][4];
#pragma unroll
            for (int mt = 0; mt < 2; mt++) {
                ldsm_x4(ah[mt], base + GO_AH + offA[ks][mt]);
                ldsm_x4(al[mt], base + GO_AL + offA[ks][mt]);
            }
#pragma unroll
            for (int nt = 0; nt < 4; nt++)
                ldsm_x4(bfrag[nt], base + GO_BH + offB[ks][nt]);
#pragma unroll
            for (int mt = 0; mt < 2; mt++)
#pragma unroll
                for (int nt = 0; nt < 4; nt++) {
                    mma_f16(acc[mt * 8 + nt * 2 + 0], ah[mt], bfrag[nt][0], bfrag[nt][2]);
                    mma_f16(acc[mt * 8 + nt * 2 + 1], ah[mt], bfrag[nt][1], bfrag[nt][3]);
                }
#pragma unroll
            for (int mt = 0; mt < 2; mt++)
#pragma unroll
                for (int nt = 0; nt < 4; nt++) {
                    mma_f16(acc[mt * 8 + nt * 2 + 0], al[mt], bfrag[nt][0], bfrag[nt][2]);
                    mma_f16(acc[mt * 8 + nt * 2 + 1], al[mt], bfrag[nt][1], bfrag[nt][3]);
                }
#pragma unroll
            for (int nt = 0; nt < 4; nt++)
                ldsm_x4(bfrag[nt], base + GO_BL + offB[ks][nt]);
#pragma unroll
            for (int mt = 0; mt < 2; mt++)
#pragma unroll
                for (int nt = 0; nt < 4; nt++) {
                    mma_f16(acc[mt * 8 + nt * 2 + 0], ah[mt], bfrag[nt][0], bfrag[nt][2]);
                    mma_f16(acc[mt * 8 + nt * 2 + 1], ah[mt], bfrag[nt][1], bfrag[nt][3]);
                }
        }
    }
#undef GLOAD

#pragma unroll
    for (int mt = 0; mt < 2; mt++) {
#pragma unroll
        for (int nt = 0; nt < 8; nt++) {
            const float* a4 = acc[mt * 8 + nt];
            int col  = n0 + wn * 64 + nt * 8 + ((lane & 3) << 1);
            float bb0 = bias[col], bb1 = bias[col + 1];
            int row0 = m0 + wm * 32 + mt * 16 + (lane >> 2);
            int row1 = row0 + 8;
            float v0 = fmaxf(a4[0] + bb0, 0.f), v1 = fmaxf(a4[1] + bb1, 0.f);
            float v2 = fmaxf(a4[2] + bb0, 0.f), v3 = fmaxf(a4[3] + bb1, 0.f);
            *reinterpret_cast<float2*>(g_g + (long)row0 * N + col) = make_float2(v0, v1);
            *reinterpret_cast<float2*>(g_g + (long)row1 * N + col) = make_float2(v2, v3);
        }
    }
}

// ---------------- pre-passes ------------------------------------------------
__global__ __launch_bounds__(256) void k_splitx(const float* __restrict__ x)
{
    if (blockIdx.x == 0 && threadIdx.x < EQ) {
        g_cnt[threadIdx.x] = 0;
        g_cursor[threadIdx.x] = 0;
    }
    long i = (long)(blockIdx.x * 256 + threadIdx.x) * 4;
    if (i >= (long)BQ * DQ) return;
    float4 v = *reinterpret_cast<const float4*>(x + i);
    __half2 h0, h1, l0, l1;
    h0.x = __float2half_rn(v.x); h0.y = __float2half_rn(v.y);
    h1.x = __float2half_rn(v.z); h1.y = __float2half_rn(v.w);
    l0.x = __float2half_rn(v.x - __half2float(h0.x));
    l0.y = __float2half_rn(v.y - __half2float(h0.y));
    l1.x = __float2half_rn(v.z - __half2float(h1.x));
    l1.y = __float2half_rn(v.w - __half2float(h1.y));
    *reinterpret_cast<uint2*>(g_x + i) = make_uint2(
        *reinterpret_cast<uint32_t*>(&h0), *reinterpret_cast<uint32_t*>(&h1));
    *reinterpret_cast<uint2*>(g_xl + i) = make_uint2(
        *reinterpret_cast<uint32_t*>(&l0), *reinterpret_cast<uint32_t*>(&l1));
}

// W [E][K][N] f32 -> Wh [E][N][K] fp16; 64k x 32n tile, 16B stores
__global__ __launch_bounds__(256) void k_splitw(
    const float* __restrict__ src, __half* __restrict__ dh, int K, int N)
{
    __shared__ float t[64][33];
    const int e  = blockIdx.z;
    const int n0 = blockIdx.x * 32;
    const int k0 = blockIdx.y * 64;
    const int tid = threadIdx.x;
    const float* S = src + (long)e * K * N;
#pragma unroll
    for (int i = 0; i < 2; i++) {
        int kr = (tid >> 3) + i * 32;
        int n4 = tid & 7;
        float4 v = *reinterpret_cast<const float4*>(S + (long)(k0 + kr) * N + n0 + n4 * 4);
        t[kr][n4 * 4 + 0] = v.x;
        t[kr][n4 * 4 + 1] = v.y;
        t[kr][n4 * 4 + 2] = v.z;
        t[kr][n4 * 4 + 3] = v.w;
    }
    __syncthreads();
    {
        int n = tid >> 3, kq = tid & 7;
        uint4 u;
        uint32_t* up = reinterpret_cast<uint32_t*>(&u);
#pragma unroll
        for (int j = 0; j < 4; j++) {
            __half2 h;
            h.x = __float2half_rn(t[kq * 8 + j * 2 + 0][n]);
            h.y = __float2half_rn(t[kq * 8 + j * 2 + 1][n]);
            up[j] = *reinterpret_cast<uint32_t*>(&h);
        }
        long o = (long)e * N * K + (long)(n0 + n) * K + k0 + kq * 8;
        *reinterpret_cast<uint4*>(dh + o) = u;
    }
}

// Wg1 [K=1024][N=512] f32 -> [N][K] fp16 hi + lo (32x32 transpose)
__global__ __launch_bounds__(256) void k_splitwg(const float* __restrict__ src)
{
    __shared__ float t[32][33];
    const int n0 = blockIdx.x * 32;
    const int k0 = blockIdx.y * 32;
    const int tid = threadIdx.x;
    {
        int kr = tid >> 3, n4 = tid & 7;
        float4 v = *reinterpret_cast<const float4*>(src + (long)(k0 + kr) * GQ + n0 + n4 * 4);
        t[kr][n4 * 4 + 0] = v.x;
        t[kr][n4 * 4 + 1] = v.y;
        t[kr][n4 * 4 + 2] = v.z;
        t[kr][n4 * 4 + 3] = v.w;
    }
    __syncthreads();
    {
        int n = tid >> 3, kq = tid & 7;
        float v0 = t[kq * 4 + 0][n], v1 = t[kq * 4 + 1][n];
        float v2 = t[kq * 4 + 2][n], v3 = t[kq * 4 + 3][n];
        __half2 h0, h1, l0, l1;
        h0.x = __float2half_rn(v0); h0.y = __float2half_rn(v1);
        h1.x = __float2half_rn(v2); h1.y = __float2half_rn(v3);
        l0.x = __float2half_rn(v0 - __half2float(h0.x));
        l0.y = __float2half_rn(v1 - __half2float(h0.y));
        l1.x = __float2half_rn(v2 - __half2float(h1.x));
        l1.y = __float2half_rn(v3 - __half2float(h1.y));
        long o = (long)(n0 + n) * DQ + k0 + kq * 4;
        *reinterpret_cast<uint2*>(g_wg1h + o) = make_uint2(
            *reinterpret_cast<uint32_t*>(&h0), *reinterpret_cast<uint32_t*>(&h1));
        *reinterpret_cast<uint2*>(g_wg1l + o) = make_uint2(
            *reinterpret_cast<uint32_t*>(&l0), *reinterpret_cast<uint32_t*>(&l1));
    }
}

// ---------------- small kernels ------------------------------------------
__global__ __launch_bounds__(128) void k_gate2(const float* __restrict__ Wg2,
                                               const float* __restrict__ bg2)
{
    int b    = blockIdx.x * 4 + (threadIdx.x >> 5);
    int lane = threadIdx.x & 31;
    const float* grow = g_g + (long)b * GQ;

    float acc[8] = {0, 0, 0, 0, 0, 0, 0, 0};
    for (int k = lane; k < GQ; k += 32) {
        float gv = grow[k];
        const float* w = Wg2 + k * 8;
#pragma unroll
        for (int e = 0; e < 8; e++) acc[e] = fmaf(gv, w[e], acc[e]);
    }
#pragma unroll
    for (int e = 0; e < 8; e++) {
#pragma unroll
        for (int o = 16; o; o >>= 1) acc[e] += __shfl_xor_sync(0xffffffffu, acc[e], o);
    }
    if (lane == 0) {
        float l[8], m = -1e30f;
#pragma unroll
        for (int e = 0; e < 8; e++) { l[e] = acc[e] + bg2[e]; m = fmaxf(m, l[e]); }
        float s = 0.f;
#pragma unroll
        for (int e = 0; e < 8; e++) { l[e] = expf(l[e] - m); s += l[e]; }
        float inv = 1.f / s;
#pragma unroll
        for (int e = 0; e < 8; e++) { l[e] *= inv; g_gatew[b * 8 + e] = l[e]; }
        int i0 = 0;
#pragma unroll
        for (int e = 1; e < 8; e++) if (l[e] > l[i0]) i0 = e;
        int i1 = -1;
#pragma unroll
        for (int e = 0; e < 8; e++) {
            if (e == i0) continue;
            if (i1 < 0 || l[e] > l[i1]) i1 = e;
        }
        float w0 = l[i0], w1 = l[i1];
        float mm = fmaxf(w0, w1);
        float e0 = expf(w0 - mm), e1 = expf(w1 - mm);
        float si = 1.f / (e0 + e1);
        g_topidx[2 * b]     = i0;
        g_topidx[2 * b + 1] = i1;
        g_topw[2 * b]       = e0 * si;
        g_topw[2 * b + 1]   = e1 * si;
        atomicAdd(&g_cnt[i0], 1);
        atomicAdd(&g_cnt[i1], 1);
    }
}

// fused: offsets + tile list + usage reduction + load-balance loss
__global__ __launch_bounds__(256) void k_route(float* out, int out_size)
{
    __shared__ float sh[256];
    __shared__ float susage[EQ];
    const int t = threadIdx.x;

    if (t == 0) {
        int s = 0, idx = 0;
        for (int e = 0; e < EQ; e++) {
            g_off[e] = s;
            int c = g_cnt[e];
            s += c;
            int nt = (c + TM - 1) / TM;
            for (int tt = 0; tt < nt; tt++) g_tiles[idx++] = e | (tt << 8);
        }
        g_off[EQ] = s;
        g_ntiles = idx;
    }

    for (int e = 0; e < EQ; e++) {
        float s = 0.f;
        for (int b = t; b < BQ; b += 256) s += g_gatew[b * 8 + e];
        sh[t] = s;
        __syncthreads();
        for (int o = 128; o; o >>= 1) {
            if (t < o) sh[t] += sh[t + o];
            __syncthreads();
        }
        if (t == 0) susage[e] = sh[0];
        __syncthreads();
    }
    if (t == 0 && out_size > BQ * DOUTQ) {
        float acc = 0.f;
        for (int e = 0; e < EQ; e++) {
            float dd = susage[e] / (float)BQ - 1.0f / (float)EQ;
            acc += dd * dd;
        }
        out[BQ * DOUTQ] = acc / (float)EQ;
    }
}

__global__ void k_scatter()
{
    int b = blockIdx.x * blockDim.x + threadIdx.x;
    if (b >= BQ) return;
#pragma unroll
    for (int s = 0; s < 2; s++) {
        int e = g_topidx[2 * b + s];
        int p = g_off[e] + atomicAdd(&g_cursor[e], 1);
        g_ptok[p]         = b;
        g_pidx[2 * b + s] = p;
    }
}

__global__ __launch_bounds__(256) void k_combine(float* __restrict__ out)
{
    int b  = blockIdx.x;
    int p0 = g_pidx[2 * b], p1 = g_pidx[2 * b + 1];
    float w0 = g_topw[2 * b], w1 = g_topw[2 * b + 1];
    const float4* y0 = reinterpret_cast<const float4*>(g_y + (long)p0 * DOUTQ);
    const float4* y1 = reinterpret_cast<const float4*>(g_y + (long)p1 * DOUTQ);
    float4* o = reinterpret_cast<float4*>(out + (long)b * DOUTQ);
    int t = threadIdx.x;
    float4 a = y0[t], c = y1[t];
    o[t] = make_float4(w0 * a.x + w1 * c.x, w0 * a.y + w1 * c.y,
                       w0 * a.z + w1 * c.z, w0 * a.w + w1 * c.w);
}

// ---------------- launch --------------------------------------------------
extern "C" void kernel_launch(void* const* d_in, const int* in_sizes, int n_in,
                              void* d_out, int out_size)
{
    const float* x   = (const float*)d_in[0];
    const float* W1  = (const float*)d_in[1];
    const float* b1  = (const float*)d_in[2];
    const float* W2  = (const float*)d_in[3];
    const float* b2  = (const float*)d_in[4];
    const float* W3  = (const float*)d_in[5];
    const float* b3  = (const float*)d_in[6];
    const float* Wg1 = (const float*)d_in[7];
    const float* bg1 = (const float*)d_in[8];
    const float* Wg2 = (const float*)d_in[9];
    const float* bg2 = (const float*)d_in[10];
    float* out = (float*)d_out;

    float* p_y;
    int* p_ptok;
    __half *p_x, *p_w1h, *p_w2h, *p_w3h, *p_h1, *p_h2;
    cudaGetSymbolAddress((void**)&p_y,    g_y);
    cudaGetSymbolAddress((void**)&p_ptok, g_ptok);
    cudaGetSymbolAddress((void**)&p_x,    g_x);
    cudaGetSymbolAddress((void**)&p_w1h,  g_w1h);
    cudaGetSymbolAddress((void**)&p_w2h,  g_w2h);
    cudaGetSymbolAddress((void**)&p_w3h,  g_w3h);
    cudaGetSymbolAddress((void**)&p_h1,   g_h1);
    cudaGetSymbolAddress((void**)&p_h2,   g_h2);

    cudaFuncSetAttribute(moe_f16_gemm,
                         cudaFuncAttributeMaxDynamicSharedMemorySize, SMEM_SZ);
    cudaFuncSetAttribute(gate_f16_gemm,
                         cudaFuncAttributeMaxDynamicSharedMemorySize, GSMEM);

    // side stream + fork/join events (created per call; not destroyed —
    // destroying a capture-participating stream would invalidate capture)
    cudaStream_t sB;
    cudaEvent_t evF, evJ;
    cudaStreamCreateWithFlags(&sB, cudaStreamNonBlocking);
    cudaEventCreateWithFlags(&evF, cudaEventDisableTiming);
    cudaEventCreateWithFlags(&evJ, cudaEventDisableTiming);

    // ---- fork: weight conversions on side stream
    cudaEventRecord(evF, 0);
    cudaStreamWaitEvent(sB, evF, 0);
    k_splitw<<<dim3(HQ / 32, DQ / 64, EQ), 256, 0, sB>>>(W1, p_w1h, DQ, HQ);
    k_splitw<<<dim3(H2Q / 32, HQ / 64, EQ), 256, 0, sB>>>(W2, p_w2h, HQ, H2Q);
    k_splitw<<<dim3(DOUTQ / 32, H2Q / 64, EQ), 256, 0, sB>>>(W3, p_w3h, H2Q, DOUTQ);
    cudaEventRecord(evJ, sB);

    // ---- main stream: x/Wg1 converts + gate chain + routing
    k_splitx<<<(BQ * DQ / 4 + 255) / 256, 256>>>(x);   // also zeroes counters
    k_splitwg<<<dim3(GQ / 32, DQ / 32, 1), 256>>>(Wg1);
    gate_f16_gemm<<<dim3(GQ / TN, BQ / TM, 1), 256, GSMEM>>>(bg1);
    k_gate2<<<BQ / 4, 128>>>(Wg2, bg2);
    k_route<<<1, 256>>>(out, out_size);
    k_scatter<<<BQ / 256, 256>>>();

    // ---- join: expert layers need converted weights
    cudaStreamWaitEvent(0, evJ, 0);

    {
        dim3 grid(HQ / TN, MAXTILES, 1);
        moe_f16_gemm<<<grid, 256, SMEM_SZ>>>(
            p_x, p_w1h, b1, p_h1, nullptr, p_ptok, DQ, HQ, 1);
    }
    {
        dim3 grid(H2Q / TN, MAXTILES, 1);
        moe_f16_gemm<<<grid, 256, SMEM_SZ>>>(
            p_h1, p_w2h, b2, p_h2, nullptr, nullptr, HQ, H2Q, 1);
    }
    {
        dim3 grid(DOUTQ / TN, MAXTILES, 1);
        moe_f16_gemm<<<grid, 256, SMEM_SZ>>>(
            p_h2, p_w3h, b3, nullptr, p_y, nullptr, H2Q, DOUTQ, 0);
    }
    k_combine<<<BQ, 256>>>(out);
}